// round 10
// baseline (speedup 1.0000x reference)
#include <cuda_runtime.h>
#include <math.h>

#define NN 20000
#define EE 320000
#define DD 128
#define SCAP 160          // smem score slots per node (max in-degree here ~45)
#define LN_EPS 1e-5f
#define NBLK 1184         // 148 SMs x 8 blocks -- all co-resident (64 regs, small smem)
#define SCB 157           // scan blocks: 157*128 = 20096 >= NN

// ---------------- scratch (no allocations allowed) ----------------
__device__ int   g_counts[NN];          // zero at load; reset each call in offsets phase
__device__ int   g_off[NN + 1];
__device__ int   g_cur[NN];
__device__ int   g_csr[EE];
__device__ int   g_bsum[SCB];
__device__ int   g_boff[SCB];
__device__ volatile unsigned g_gen = 0; // grid-barrier generation (monotonic)
__device__ unsigned g_arrive = 0;       // grid-barrier arrive counter (self-resetting)

// ---------------- grid barrier (all NBLK blocks guaranteed resident) ----------------
__device__ __forceinline__ void grid_sync() {
    __syncthreads();
    if (threadIdx.x == 0) {
        __threadfence();
        unsigned gen = g_gen;
        if (atomicAdd(&g_arrive, 1u) == NBLK - 1u) {
            g_arrive = 0;
            __threadfence();
            g_gen = gen + 1u;
        } else {
            while (g_gen == gen) { }
            __threadfence();
        }
    }
    __syncthreads();
}

__device__ __forceinline__ int wscan_incl(int v, int l) {
    #pragma unroll
    for (int o = 1; o < 32; o <<= 1) {
        int u = __shfl_up_sync(0xffffffffu, v, o);
        if (l >= o) v += u;
    }
    return v;
}

// ---------------- helpers ----------------
__device__ __forceinline__ float gelu_erf(float x) {
    return 0.5f * x * (1.0f + erff(x * 0.70710678118654752440f));
}

__device__ __forceinline__ float wred(float a) {
    #pragma unroll
    for (int o = 16; o; o >>= 1) a += __shfl_xor_sync(0xffffffffu, a, o);
    return a;
}

__device__ __forceinline__ void wred2(float& a, float& b) {
    #pragma unroll
    for (int o = 16; o; o >>= 1) {
        a += __shfl_xor_sync(0xffffffffu, a, o);
        b += __shfl_xor_sync(0xffffffffu, b, o);
    }
}

__device__ __forceinline__ float bred1(float a, volatile float* sb) {
    #pragma unroll
    for (int o = 16; o; o >>= 1) a += __shfl_down_sync(0xffffffffu, a, o);
    if ((threadIdx.x & 31) == 0) sb[threadIdx.x >> 5] = a;
    __syncthreads();
    a = sb[0] + sb[1] + sb[2] + sb[3];
    __syncthreads();
    return a;
}

__device__ __forceinline__ float2 bred2(float a, float b, volatile float* sb) {
    #pragma unroll
    for (int o = 16; o; o >>= 1) {
        a += __shfl_down_sync(0xffffffffu, a, o);
        b += __shfl_down_sync(0xffffffffu, b, o);
    }
    int w = threadIdx.x >> 5;
    if ((threadIdx.x & 31) == 0) { sb[w] = a; sb[w + 4] = b; }
    __syncthreads();
    float2 r;
    r.x = sb[0] + sb[1] + sb[2] + sb[3];
    r.y = sb[4] + sb[5] + sb[6] + sb[7];
    __syncthreads();
    return r;
}

#define LD4(p)  (*(const float4*)(p))
// streaming (evict-first) load — edge-weight data is read exactly once
#define LDS4(p) (__ldcs((const float4*)(p)))

// ---------------- one persistent kernel: CSR build + node processing ----------------
__global__ __launch_bounds__(128, 8) void k_all(
    const float* __restrict__ feat,  const float* __restrict__ query,
    const int*   __restrict__ src,   const int* __restrict__ dst,
    const float* __restrict__ ukw, const float* __restrict__ ukb,
    const float* __restrict__ vkw, const float* __restrict__ vkb,
    const float* __restrict__ ekw, const float* __restrict__ ekb,
    const float* __restrict__ uvw, const float* __restrict__ uvb,
    const float* __restrict__ vvw, const float* __restrict__ vvb,
    const float* __restrict__ evw, const float* __restrict__ evb,
    const float* __restrict__ nodew, const float* __restrict__ nodeb,
    const float* __restrict__ kg,  const float* __restrict__ kbt,
    const float* __restrict__ vg,  const float* __restrict__ vbt,
    const float* __restrict__ ng,  const float* __restrict__ nbt,
    float* __restrict__ out, float* __restrict__ attn)
{
    __shared__ float sb[8];
    __shared__ float swmax[4];
    __shared__ float sacc[4][DD];
    __shared__ float sscore[SCAP];
    __shared__ int   ibuf[4];

    const int bid = blockIdx.x;
    const int t = threadIdx.x;
    const int w = t >> 5;
    const int l = t & 31;
    const int c = l << 2;
    const int gtid = bid * 128 + t;

    // ================= prelude: CSR build =================
    // phase A: histogram
    for (int i = gtid; i < EE; i += NBLK * 128)
        atomicAdd(&g_counts[dst[i]], 1);
    grid_sync();

    // phase B1: block-local scan (blocks 0..SCB-1, 128 nodes each)
    int ex_local = 0;
    if (bid < SCB) {
        const int node = bid * 128 + t;
        const int cval = (node < NN) ? g_counts[node] : 0;
        int incl = wscan_incl(cval, l);
        if (l == 31) ibuf[w] = incl;
        __syncthreads();
        if (t < 4) {
            int v = ibuf[t];
            #pragma unroll
            for (int o = 1; o < 4; o <<= 1) {
                int u = __shfl_up_sync(0xFu, v, o);
                if (t >= o) v += u;
            }
            ibuf[t] = v;
        }
        __syncthreads();
        ex_local = ((w == 0) ? 0 : ibuf[w - 1]) + incl - cval;
        if (t == 127) g_bsum[bid] = ibuf[3];
        __syncthreads();
    }
    grid_sync();

    // phase B2: block 0 scans the SCB block sums (2 slots/thread, padded to 256)
    if (bid == 0) {
        const int s0 = 2 * t, s1 = 2 * t + 1;
        const int v0 = (s0 < SCB) ? g_bsum[s0] : 0;
        const int v1 = (s1 < SCB) ? g_bsum[s1] : 0;
        const int pair = v0 + v1;
        int incl = wscan_incl(pair, l);
        if (l == 31) ibuf[w] = incl;
        __syncthreads();
        if (t < 4) {
            int v = ibuf[t];
            #pragma unroll
            for (int o = 1; o < 4; o <<= 1) {
                int u = __shfl_up_sync(0xFu, v, o);
                if (t >= o) v += u;
            }
            ibuf[t] = v;
        }
        __syncthreads();
        const int ex = ((w == 0) ? 0 : ibuf[w - 1]) + incl - pair;
        if (s0 < SCB) g_boff[s0] = ex;
        if (s1 < SCB) g_boff[s1] = ex + v0;
        if (t == 127) g_off[NN] = ibuf[3];
    }
    grid_sync();

    // phase B3: write offsets, reset counters
    if (bid < SCB) {
        const int node = bid * 128 + t;
        if (node < NN) {
            const int v = g_boff[bid] + ex_local;
            g_off[node] = v;
            g_cur[node] = v;
            g_counts[node] = 0;
        }
    }
    grid_sync();

    // phase C: scatter edge ids
    for (int i = gtid; i < EE; i += NBLK * 128) {
        int p = atomicAdd(&g_cur[dst[i]], 1);
        g_csr[p] = i;
    }
    grid_sync();

    // ================= node processing (persistent loop) =================
    const float invD = 1.0f / DD;
    const float4 kg4 = LD4(kg + c);
    const float4 kb4 = LD4(kbt + c);
    const float4 vg4 = LD4(vg + c);
    const float4 vb4 = LD4(vbt + c);
    const float ngv = ng[t];
    const float nbv = nbt[t];

    for (int n = bid; n < NN; n += NBLK) {
        const int off = g_off[n];
        const int deg = g_off[n + 1] - off;

        const float4 fv4 = LD4(feat  + n * DD + c);
        const float4 q4  = LD4(query + n * DD + c);

        // ---- pass 1: key edge-FFN + LN + score (warp per edge, no barriers) ----
        float wmax = -3.402823466e38f;
        for (int i = w; i < deg; i += 4) {
            const int e = g_csr[off + i];
            const int s = src[e];
            const long eb = (long)e * DD + c;
            const float4 fu = LD4(feat + (long)s * DD + c);
            const float4 a1 = LDS4(ukw + eb), b1 = LDS4(ukb + eb);
            const float4 a2 = LDS4(vkw + eb), b2 = LDS4(vkb + eb);
            const float4 a3 = LDS4(ekw + eb), b3 = LDS4(ekb + eb);
            float4 h;
            h.x = fmaf(fu.x, a1.x, b1.x) + fmaf(fv4.x, a2.x, b2.x);
            h.y = fmaf(fu.y, a1.y, b1.y) + fmaf(fv4.y, a2.y, b2.y);
            h.z = fmaf(fu.z, a1.z, b1.z) + fmaf(fv4.z, a2.z, b2.z);
            h.w = fmaf(fu.w, a1.w, b1.w) + fmaf(fv4.w, a2.w, b2.w);
            h.x = gelu_erf(h.x); h.y = gelu_erf(h.y);
            h.z = gelu_erf(h.z); h.w = gelu_erf(h.w);
            h.x = fmaf(h.x, a3.x, b3.x);
            h.y = fmaf(h.y, a3.y, b3.y);
            h.z = fmaf(h.z, a3.z, b3.z);
            h.w = fmaf(h.w, a3.w, b3.w);
            float sum = h.x + h.y + h.z + h.w;
            float sq  = h.x * h.x + h.y * h.y + h.z * h.z + h.w * h.w;
            wred2(sum, sq);
            const float m   = sum * invD;
            const float var = fmaxf(sq * invD - m * m, 0.0f);
            const float rs  = rsqrtf(var + LN_EPS);
            float dot = ((h.x - m) * rs * kg4.x + kb4.x) * q4.x
                      + ((h.y - m) * rs * kg4.y + kb4.y) * q4.y
                      + ((h.z - m) * rs * kg4.z + kb4.z) * q4.z
                      + ((h.w - m) * rs * kg4.w + kb4.w) * q4.w;
            dot = wred(dot);
            if (l == 0 && i < SCAP) sscore[i] = dot;
            wmax = fmaxf(wmax, dot);
        }
        if (l == 0) swmax[w] = wmax;
        __syncthreads();
        const float smax = fmaxf(fmaxf(swmax[0], swmax[1]), fmaxf(swmax[2], swmax[3]));

        // ---- softmax denominator (parallel over threads, smem scores) ----
        float part = 0.0f;
        for (int i = t; i < deg; i += 128) part += __expf(sscore[i] - smax);
        const float ssum = bred1(part, sb);
        const float inv = (deg > 0) ? (1.0f / ssum) : 0.0f;

        // ---- pass 2: value edge-FFN + LN + weighted accumulation ----
        float4 acc = make_float4(0.f, 0.f, 0.f, 0.f);
        for (int i = w; i < deg; i += 4) {
            const int e = g_csr[off + i];
            const float a = __expf(sscore[i] - smax) * inv;
            if (l == 0) __stcs(attn + e, a);
            const int s = src[e];
            const long eb = (long)e * DD + c;
            const float4 fu = LD4(feat + (long)s * DD + c);
            const float4 a1 = LDS4(uvw + eb), b1 = LDS4(uvb + eb);
            const float4 a2 = LDS4(vvw + eb), b2 = LDS4(vvb + eb);
            const float4 a3 = LDS4(evw + eb), b3 = LDS4(evb + eb);
            float4 h;
            h.x = fmaf(fu.x, a1.x, b1.x) + fmaf(fv4.x, a2.x, b2.x);
            h.y = fmaf(fu.y, a1.y, b1.y) + fmaf(fv4.y, a2.y, b2.y);
            h.z = fmaf(fu.z, a1.z, b1.z) + fmaf(fv4.z, a2.z, b2.z);
            h.w = fmaf(fu.w, a1.w, b1.w) + fmaf(fv4.w, a2.w, b2.w);
            h.x = gelu_erf(h.x); h.y = gelu_erf(h.y);
            h.z = gelu_erf(h.z); h.w = gelu_erf(h.w);
            h.x = fmaf(h.x, a3.x, b3.x);
            h.y = fmaf(h.y, a3.y, b3.y);
            h.z = fmaf(h.z, a3.z, b3.z);
            h.w = fmaf(h.w, a3.w, b3.w);
            float sum = h.x + h.y + h.z + h.w;
            float sq  = h.x * h.x + h.y * h.y + h.z * h.z + h.w * h.w;
            wred2(sum, sq);
            const float m   = sum * invD;
            const float var = fmaxf(sq * invD - m * m, 0.0f);
            const float rs  = rsqrtf(var + LN_EPS);
            acc.x = fmaf(((h.x - m) * rs) * vg4.x + vb4.x, a, acc.x);
            acc.y = fmaf(((h.y - m) * rs) * vg4.y + vb4.y, a, acc.y);
            acc.z = fmaf(((h.z - m) * rs) * vg4.z + vb4.z, a, acc.z);
            acc.w = fmaf(((h.w - m) * rs) * vg4.w + vb4.w, a, acc.w);
        }
        *(float4*)&sacc[w][c] = acc;
        __syncthreads();
        const float aT = sacc[0][t] + sacc[1][t] + sacc[2][t] + sacc[3][t];

        // ---- node FFN + residual + LN ----
        const float w0 = __ldcs(nodew + (n * 2 + 0) * DD + t);
        const float b0 = __ldcs(nodeb + (n * 2 + 0) * DD + t);
        const float w1 = __ldcs(nodew + (n * 2 + 1) * DD + t);
        const float b1 = __ldcs(nodeb + (n * 2 + 1) * DD + t);
        float h = gelu_erf(fmaf(aT, w0, b0));
        h = fmaf(h, w1, b1);
        const float rsd = aT + h;
        float2 r = bred2(rsd, rsd * rsd, sb);
        const float m   = r.x * invD;
        const float var = fmaxf(r.y * invD - m * m, 0.0f);
        out[n * DD + t] = (rsd - m) * rsqrtf(var + LN_EPS) * ngv + nbv;
        __syncthreads();   // protect sscore/sacc reuse across node iterations
    }
}

// ---------------- launch ----------------
extern "C" void kernel_launch(void* const* d_in, const int* in_sizes, int n_in,
                              void* d_out, int out_size) {
    const float* feat  = (const float*)d_in[0];
    const float* query = (const float*)d_in[1];
    const int*   src   = (const int*)d_in[2];
    const int*   dst   = (const int*)d_in[3];
    const float* ukw = (const float*)d_in[4];
    const float* ukb = (const float*)d_in[5];
    const float* vkw = (const float*)d_in[6];
    const float* vkb = (const float*)d_in[7];
    const float* ekw = (const float*)d_in[8];
    const float* ekb = (const float*)d_in[9];
    const float* uvw = (const float*)d_in[10];
    const float* uvb = (const float*)d_in[11];
    const float* vvw = (const float*)d_in[12];
    const float* vvb = (const float*)d_in[13];
    const float* evw = (const float*)d_in[14];
    const float* evb = (const float*)d_in[15];
    const float* nodew = (const float*)d_in[16];
    const float* nodeb = (const float*)d_in[17];
    const float* kg  = (const float*)d_in[18];
    const float* vg  = (const float*)d_in[19];
    const float* ng  = (const float*)d_in[20];
    const float* kbt = (const float*)d_in[21];
    const float* vbt = (const float*)d_in[22];
    const float* nbt = (const float*)d_in[23];

    float* out  = (float*)d_out;            // [N, D]
    float* attn = out + (long)NN * DD;      // [E, 1]

    k_all<<<NBLK, 128>>>(feat, query, src, dst,
                         ukw, ukb, vkw, vkb, ekw, ekb,
                         uvw, uvb, vvw, vvb, evw, evb,
                         nodew, nodeb,
                         kg, kbt, vg, vbt, ng, nbt,
                         out, attn);
}

// round 11
// speedup vs baseline: 1.1172x; 1.1172x over previous
#include <cuda_runtime.h>
#include <math.h>

#define NN 20000
#define EE 320000
#define DD 128
#define SCAP 160          // smem score slots per node (max in-degree here ~45)
#define LN_EPS 1e-5f
#define NBLK 1184         // 148 SMs x 8 blocks -- all co-resident (64 regs, small smem)
#define SCB 157           // scan blocks: 157*128 = 20096 >= NN

// ---------------- scratch (no allocations allowed) ----------------
__device__ int   g_counts[NN];          // zero at load; reset each call in offsets phase
__device__ int   g_off[NN + 1];
__device__ int   g_cur[NN];
__device__ int   g_csr[EE];
__device__ int   g_bsum[SCB];
__device__ int   g_boff[SCB];
__device__ int   g_ticket;              // dynamic node dispenser (reset each call)
__device__ volatile unsigned g_gen = 0; // grid-barrier generation (monotonic)
__device__ unsigned g_arrive = 0;       // grid-barrier arrive counter (self-resetting)

// ---------------- grid barrier (all NBLK blocks guaranteed resident) ----------------
__device__ __forceinline__ void grid_sync() {
    __syncthreads();
    if (threadIdx.x == 0) {
        __threadfence();
        unsigned gen = g_gen;
        if (atomicAdd(&g_arrive, 1u) == NBLK - 1u) {
            g_arrive = 0;
            __threadfence();
            g_gen = gen + 1u;
        } else {
            while (g_gen == gen) { }
            __threadfence();
        }
    }
    __syncthreads();
}

__device__ __forceinline__ int wscan_incl(int v, int l) {
    #pragma unroll
    for (int o = 1; o < 32; o <<= 1) {
        int u = __shfl_up_sync(0xffffffffu, v, o);
        if (l >= o) v += u;
    }
    return v;
}

// ---------------- helpers ----------------
__device__ __forceinline__ float gelu_erf(float x) {
    return 0.5f * x * (1.0f + erff(x * 0.70710678118654752440f));
}

__device__ __forceinline__ float wred(float a) {
    #pragma unroll
    for (int o = 16; o; o >>= 1) a += __shfl_xor_sync(0xffffffffu, a, o);
    return a;
}

__device__ __forceinline__ void wred2(float& a, float& b) {
    #pragma unroll
    for (int o = 16; o; o >>= 1) {
        a += __shfl_xor_sync(0xffffffffu, a, o);
        b += __shfl_xor_sync(0xffffffffu, b, o);
    }
}

__device__ __forceinline__ float bred1(float a, volatile float* sb) {
    #pragma unroll
    for (int o = 16; o; o >>= 1) a += __shfl_down_sync(0xffffffffu, a, o);
    if ((threadIdx.x & 31) == 0) sb[threadIdx.x >> 5] = a;
    __syncthreads();
    a = sb[0] + sb[1] + sb[2] + sb[3];
    __syncthreads();
    return a;
}

__device__ __forceinline__ float2 bred2(float a, float b, volatile float* sb) {
    #pragma unroll
    for (int o = 16; o; o >>= 1) {
        a += __shfl_down_sync(0xffffffffu, a, o);
        b += __shfl_down_sync(0xffffffffu, b, o);
    }
    int w = threadIdx.x >> 5;
    if ((threadIdx.x & 31) == 0) { sb[w] = a; sb[w + 4] = b; }
    __syncthreads();
    float2 r;
    r.x = sb[0] + sb[1] + sb[2] + sb[3];
    r.y = sb[4] + sb[5] + sb[6] + sb[7];
    __syncthreads();
    return r;
}

#define LD4(p)  (*(const float4*)(p))
// streaming (evict-first) load — edge-weight data is read exactly once
#define LDS4(p) (__ldcs((const float4*)(p)))

// ---------------- one persistent kernel: CSR build + ticketed node processing ----------------
__global__ __launch_bounds__(128, 8) void k_all(
    const float* __restrict__ feat,  const float* __restrict__ query,
    const int*   __restrict__ src,   const int* __restrict__ dst,
    const float* __restrict__ ukw, const float* __restrict__ ukb,
    const float* __restrict__ vkw, const float* __restrict__ vkb,
    const float* __restrict__ ekw, const float* __restrict__ ekb,
    const float* __restrict__ uvw, const float* __restrict__ uvb,
    const float* __restrict__ vvw, const float* __restrict__ vvb,
    const float* __restrict__ evw, const float* __restrict__ evb,
    const float* __restrict__ nodew, const float* __restrict__ nodeb,
    const float* __restrict__ kg,  const float* __restrict__ kbt,
    const float* __restrict__ vg,  const float* __restrict__ vbt,
    const float* __restrict__ ng,  const float* __restrict__ nbt,
    float* __restrict__ out, float* __restrict__ attn)
{
    __shared__ float sb[8];
    __shared__ float swmax[4];
    __shared__ float sacc[4][DD];
    __shared__ float sscore[SCAP];
    __shared__ int   ibuf[4];
    __shared__ int   snode;

    const int bid = blockIdx.x;
    const int t = threadIdx.x;
    const int w = t >> 5;
    const int l = t & 31;
    const int c = l << 2;
    const int gtid = bid * 128 + t;

    // ================= prelude: CSR build =================
    // phase A: histogram
    for (int i = gtid; i < EE; i += NBLK * 128)
        atomicAdd(&g_counts[dst[i]], 1);
    grid_sync();

    // phase B1: block-local scan (blocks 0..SCB-1, 128 nodes each)
    int ex_local = 0;
    if (bid < SCB) {
        const int node = bid * 128 + t;
        const int cval = (node < NN) ? g_counts[node] : 0;
        int incl = wscan_incl(cval, l);
        if (l == 31) ibuf[w] = incl;
        __syncthreads();
        if (t < 4) {
            int v = ibuf[t];
            #pragma unroll
            for (int o = 1; o < 4; o <<= 1) {
                int u = __shfl_up_sync(0xFu, v, o);
                if (t >= o) v += u;
            }
            ibuf[t] = v;
        }
        __syncthreads();
        ex_local = ((w == 0) ? 0 : ibuf[w - 1]) + incl - cval;
        if (t == 127) g_bsum[bid] = ibuf[3];
        __syncthreads();
    }
    grid_sync();

    // phase B2: block 0 scans the SCB block sums (2 slots/thread)
    if (bid == 0) {
        const int s0 = 2 * t, s1 = 2 * t + 1;
        const int v0 = (s0 < SCB) ? g_bsum[s0] : 0;
        const int v1 = (s1 < SCB) ? g_bsum[s1] : 0;
        const int pair = v0 + v1;
        int incl = wscan_incl(pair, l);
        if (l == 31) ibuf[w] = incl;
        __syncthreads();
        if (t < 4) {
            int v = ibuf[t];
            #pragma unroll
            for (int o = 1; o < 4; o <<= 1) {
                int u = __shfl_up_sync(0xFu, v, o);
                if (t >= o) v += u;
            }
            ibuf[t] = v;
        }
        __syncthreads();
        const int ex = ((w == 0) ? 0 : ibuf[w - 1]) + incl - pair;
        if (s0 < SCB) g_boff[s0] = ex;
        if (s1 < SCB) g_boff[s1] = ex + v0;
        if (t == 127) g_off[NN] = ibuf[3];
    }
    grid_sync();

    // phase B3: write offsets, reset counters + ticket
    if (bid < SCB) {
        const int node = bid * 128 + t;
        if (node < NN) {
            const int v = g_boff[bid] + ex_local;
            g_off[node] = v;
            g_cur[node] = v;
            g_counts[node] = 0;
        }
    }
    if (bid == NBLK - 1 && t == 0) g_ticket = 0;   // reset dispenser for this call
    grid_sync();

    // phase C: scatter edge ids
    for (int i = gtid; i < EE; i += NBLK * 128) {
        int p = atomicAdd(&g_cur[dst[i]], 1);
        g_csr[p] = i;
    }
    grid_sync();

    // ================= node processing (dynamic ticketing) =================
    const float invD = 1.0f / DD;
    const float4 kg4 = LD4(kg + c);
    const float4 kb4 = LD4(kbt + c);
    const float4 vg4 = LD4(vg + c);
    const float4 vb4 = LD4(vbt + c);
    const float ngv = ng[t];
    const float nbv = nbt[t];

    for (;;) {
        if (t == 0) snode = atomicAdd(&g_ticket, 1);
        __syncthreads();                 // also protects sscore/sacc reuse
        const int n = snode;
        if (n >= NN) break;

        const int off = g_off[n];
        const int deg = g_off[n + 1] - off;

        const float4 fv4 = LD4(feat  + n * DD + c);
        const float4 q4  = LD4(query + n * DD + c);

        // ---- pass 1: key edge-FFN + LN + score (warp per edge, no barriers) ----
        float wmax = -3.402823466e38f;
        for (int i = w; i < deg; i += 4) {
            const int e = g_csr[off + i];
            const int s = src[e];
            const long eb = (long)e * DD + c;
            const float4 fu = LD4(feat + (long)s * DD + c);
            const float4 a1 = LDS4(ukw + eb), b1 = LDS4(ukb + eb);
            const float4 a2 = LDS4(vkw + eb), b2 = LDS4(vkb + eb);
            const float4 a3 = LDS4(ekw + eb), b3 = LDS4(ekb + eb);
            float4 h;
            h.x = fmaf(fu.x, a1.x, b1.x) + fmaf(fv4.x, a2.x, b2.x);
            h.y = fmaf(fu.y, a1.y, b1.y) + fmaf(fv4.y, a2.y, b2.y);
            h.z = fmaf(fu.z, a1.z, b1.z) + fmaf(fv4.z, a2.z, b2.z);
            h.w = fmaf(fu.w, a1.w, b1.w) + fmaf(fv4.w, a2.w, b2.w);
            h.x = gelu_erf(h.x); h.y = gelu_erf(h.y);
            h.z = gelu_erf(h.z); h.w = gelu_erf(h.w);
            h.x = fmaf(h.x, a3.x, b3.x);
            h.y = fmaf(h.y, a3.y, b3.y);
            h.z = fmaf(h.z, a3.z, b3.z);
            h.w = fmaf(h.w, a3.w, b3.w);
            float sum = h.x + h.y + h.z + h.w;
            float sq  = h.x * h.x + h.y * h.y + h.z * h.z + h.w * h.w;
            wred2(sum, sq);
            const float m   = sum * invD;
            const float var = fmaxf(sq * invD - m * m, 0.0f);
            const float rs  = rsqrtf(var + LN_EPS);
            float dot = ((h.x - m) * rs * kg4.x + kb4.x) * q4.x
                      + ((h.y - m) * rs * kg4.y + kb4.y) * q4.y
                      + ((h.z - m) * rs * kg4.z + kb4.z) * q4.z
                      + ((h.w - m) * rs * kg4.w + kb4.w) * q4.w;
            dot = wred(dot);
            if (l == 0 && i < SCAP) sscore[i] = dot;
            wmax = fmaxf(wmax, dot);
        }
        if (l == 0) swmax[w] = wmax;
        __syncthreads();
        const float smax = fmaxf(fmaxf(swmax[0], swmax[1]), fmaxf(swmax[2], swmax[3]));

        // ---- softmax denominator (parallel over threads, smem scores) ----
        float part = 0.0f;
        for (int i = t; i < deg; i += 128) part += __expf(sscore[i] - smax);
        const float ssum = bred1(part, sb);
        const float inv = (deg > 0) ? (1.0f / ssum) : 0.0f;

        // ---- pass 2: value edge-FFN + LN + weighted accumulation ----
        float4 acc = make_float4(0.f, 0.f, 0.f, 0.f);
        for (int i = w; i < deg; i += 4) {
            const int e = g_csr[off + i];
            const float a = __expf(sscore[i] - smax) * inv;
            if (l == 0) __stcs(attn + e, a);
            const int s = src[e];
            const long eb = (long)e * DD + c;
            const float4 fu = LD4(feat + (long)s * DD + c);
            const float4 a1 = LDS4(uvw + eb), b1 = LDS4(uvb + eb);
            const float4 a2 = LDS4(vvw + eb), b2 = LDS4(vvb + eb);
            const float4 a3 = LDS4(evw + eb), b3 = LDS4(evb + eb);
            float4 h;
            h.x = fmaf(fu.x, a1.x, b1.x) + fmaf(fv4.x, a2.x, b2.x);
            h.y = fmaf(fu.y, a1.y, b1.y) + fmaf(fv4.y, a2.y, b2.y);
            h.z = fmaf(fu.z, a1.z, b1.z) + fmaf(fv4.z, a2.z, b2.z);
            h.w = fmaf(fu.w, a1.w, b1.w) + fmaf(fv4.w, a2.w, b2.w);
            h.x = gelu_erf(h.x); h.y = gelu_erf(h.y);
            h.z = gelu_erf(h.z); h.w = gelu_erf(h.w);
            h.x = fmaf(h.x, a3.x, b3.x);
            h.y = fmaf(h.y, a3.y, b3.y);
            h.z = fmaf(h.z, a3.z, b3.z);
            h.w = fmaf(h.w, a3.w, b3.w);
            float sum = h.x + h.y + h.z + h.w;
            float sq  = h.x * h.x + h.y * h.y + h.z * h.z + h.w * h.w;
            wred2(sum, sq);
            const float m   = sum * invD;
            const float var = fmaxf(sq * invD - m * m, 0.0f);
            const float rs  = rsqrtf(var + LN_EPS);
            acc.x = fmaf(((h.x - m) * rs) * vg4.x + vb4.x, a, acc.x);
            acc.y = fmaf(((h.y - m) * rs) * vg4.y + vb4.y, a, acc.y);
            acc.z = fmaf(((h.z - m) * rs) * vg4.z + vb4.z, a, acc.z);
            acc.w = fmaf(((h.w - m) * rs) * vg4.w + vb4.w, a, acc.w);
        }
        *(float4*)&sacc[w][c] = acc;
        __syncthreads();
        const float aT = sacc[0][t] + sacc[1][t] + sacc[2][t] + sacc[3][t];

        // ---- node FFN + residual + LN ----
        const float w0 = __ldcs(nodew + (n * 2 + 0) * DD + t);
        const float b0 = __ldcs(nodeb + (n * 2 + 0) * DD + t);
        const float w1 = __ldcs(nodew + (n * 2 + 1) * DD + t);
        const float b1 = __ldcs(nodeb + (n * 2 + 1) * DD + t);
        float h = gelu_erf(fmaf(aT, w0, b0));
        h = fmaf(h, w1, b1);
        const float rsd = aT + h;
        float2 r = bred2(rsd, rsd * rsd, sb);
        const float m   = r.x * invD;
        const float var = fmaxf(r.y * invD - m * m, 0.0f);
        out[n * DD + t] = (rsd - m) * rsqrtf(var + LN_EPS) * ngv + nbv;
    }
}

// ---------------- launch ----------------
extern "C" void kernel_launch(void* const* d_in, const int* in_sizes, int n_in,
                              void* d_out, int out_size) {
    const float* feat  = (const float*)d_in[0];
    const float* query = (const float*)d_in[1];
    const int*   src   = (const int*)d_in[2];
    const int*   dst   = (const int*)d_in[3];
    const float* ukw = (const float*)d_in[4];
    const float* ukb = (const float*)d_in[5];
    const float* vkw = (const float*)d_in[6];
    const float* vkb = (const float*)d_in[7];
    const float* ekw = (const float*)d_in[8];
    const float* ekb = (const float*)d_in[9];
    const float* uvw = (const float*)d_in[10];
    const float* uvb = (const float*)d_in[11];
    const float* vvw = (const float*)d_in[12];
    const float* vvb = (const float*)d_in[13];
    const float* evw = (const float*)d_in[14];
    const float* evb = (const float*)d_in[15];
    const float* nodew = (const float*)d_in[16];
    const float* nodeb = (const float*)d_in[17];
    const float* kg  = (const float*)d_in[18];
    const float* vg  = (const float*)d_in[19];
    const float* ng  = (const float*)d_in[20];
    const float* kbt = (const float*)d_in[21];
    const float* vbt = (const float*)d_in[22];
    const float* nbt = (const float*)d_in[23];

    float* out  = (float*)d_out;            // [N, D]
    float* attn = out + (long)NN * DD;      // [E, 1]

    k_all<<<NBLK, 128>>>(feat, query, src, dst,
                         ukw, ukb, vkw, vkb, ekw, ekb,
                         uvw, uvb, vvw, vvb, evw, evb,
                         nodew, nodeb,
                         kg, kbt, vg, vbt, ng, nbt,
                         out, attn);
}

// round 12
// speedup vs baseline: 1.1814x; 1.0575x over previous
#include <cuda_runtime.h>
#include <math.h>

#define NN 20000
#define EE 320000
#define DD 128
#define SCAP 160         // smem score slots per node (max in-degree here ~45)
#define LN_EPS 1e-5f
#define NB 256           // prelude grid: 2 blocks/SM co-resident (<= 296 capacity)
#define SCB 79           // scan blocks: 79*256 = 20224 >= NN

// ---------------- scratch (no allocations allowed) ----------------
__device__ int   g_counts[NN];          // zero at load; reset each call (phase B2)
__device__ int   g_off[NN + 1];
__device__ int   g_cur[NN];
__device__ int   g_csr[EE];
__device__ int   g_bsum[SCB];
__device__ volatile unsigned g_gen = 0; // grid-barrier generation (monotonic)
__device__ unsigned g_arrive = 0;       // grid-barrier arrive counter (self-resetting)

// ---------------- grid barrier (all NB blocks guaranteed resident) ----------------
__device__ __forceinline__ void grid_sync() {
    __syncthreads();
    if (threadIdx.x == 0) {
        __threadfence();
        unsigned gen = g_gen;
        if (atomicAdd(&g_arrive, 1u) == NB - 1u) {
            g_arrive = 0;
            __threadfence();
            g_gen = gen + 1u;
        } else {
            while (g_gen == gen) { }
            __threadfence();
        }
    }
    __syncthreads();
}

__device__ __forceinline__ int wscan_incl(int v, int l) {
    #pragma unroll
    for (int o = 1; o < 32; o <<= 1) {
        int u = __shfl_up_sync(0xffffffffu, v, o);
        if (l >= o) v += u;
    }
    return v;
}

// ---------------- fused CSR build: hist -> scan -> offsets(+redundant prefix) -> scatter ----------------
__global__ __launch_bounds__(256, 2) void k_pre(const int* __restrict__ dst) {
    const int t   = threadIdx.x;
    const int bid = blockIdx.x;
    const int l   = t & 31;
    const int wid = t >> 5;
    __shared__ int wsum[8];
    __shared__ int isum[8];
    __shared__ int sbtot;

    // ---- phase A: histogram ----
    for (int i = bid * 256 + t; i < EE; i += NB * 256)
        atomicAdd(&g_counts[dst[i]], 1);
    grid_sync();

    // ---- phase B1: per-block scan over 256 nodes ----
    int ex_local = 0;
    if (bid < SCB) {
        const int node = bid * 256 + t;
        const int cval = (node < NN) ? g_counts[node] : 0;
        int incl = wscan_incl(cval, l);
        if (l == 31) wsum[wid] = incl;
        __syncthreads();
        if (t < 8) {
            int v = wsum[t];
            #pragma unroll
            for (int o = 1; o < 8; o <<= 1) {
                int u = __shfl_up_sync(0xffu, v, o);
                if (t >= o) v += u;
            }
            wsum[t] = v;
        }
        __syncthreads();
        ex_local = ((wid == 0) ? 0 : wsum[wid - 1]) + incl - cval;
        if (t == 0) sbtot = 0;           // init before reuse below
        if (t == 255) g_bsum[bid] = wsum[7];
        __syncthreads();
        if (t == 255) sbtot = wsum[7];   // keep block total in smem
        __syncthreads();
    }
    grid_sync();

    // ---- phase B2: every scan block computes its own prefix (redundant, no extra sync) ----
    if (bid < SCB) {
        int v = (t < bid) ? g_bsum[t] : 0;    // bid <= 78 < 256
        #pragma unroll
        for (int o = 16; o; o >>= 1) v += __shfl_xor_sync(0xffffffffu, v, o);
        if (l == 0) isum[wid] = v;
        __syncthreads();
        const int base = isum[0] + isum[1] + isum[2] + isum[3]
                       + isum[4] + isum[5] + isum[6] + isum[7];
        const int node = bid * 256 + t;
        if (node < NN) {
            const int off = base + ex_local;
            g_off[node] = off;
            g_cur[node] = off;
            g_counts[node] = 0;               // restore invariant for next call
        }
        if (bid == SCB - 1 && t == 0) g_off[NN] = base + sbtot;
    }
    grid_sync();

    // ---- phase C: scatter edge ids ----
    for (int i = bid * 256 + t; i < EE; i += NB * 256) {
        int p = atomicAdd(&g_cur[dst[i]], 1);
        g_csr[p] = i;
    }
}

// ---------------- helpers ----------------
__device__ __forceinline__ float gelu_erf(float x) {
    return 0.5f * x * (1.0f + erff(x * 0.70710678118654752440f));
}

__device__ __forceinline__ float wred(float a) {
    #pragma unroll
    for (int o = 16; o; o >>= 1) a += __shfl_xor_sync(0xffffffffu, a, o);
    return a;
}

__device__ __forceinline__ void wred2(float& a, float& b) {
    #pragma unroll
    for (int o = 16; o; o >>= 1) {
        a += __shfl_xor_sync(0xffffffffu, a, o);
        b += __shfl_xor_sync(0xffffffffu, b, o);
    }
}

__device__ __forceinline__ float bred1(float a, volatile float* sb) {
    #pragma unroll
    for (int o = 16; o; o >>= 1) a += __shfl_down_sync(0xffffffffu, a, o);
    if ((threadIdx.x & 31) == 0) sb[threadIdx.x >> 5] = a;
    __syncthreads();
    a = sb[0] + sb[1] + sb[2] + sb[3];
    __syncthreads();
    return a;
}

__device__ __forceinline__ float2 bred2(float a, float b, volatile float* sb) {
    #pragma unroll
    for (int o = 16; o; o >>= 1) {
        a += __shfl_down_sync(0xffffffffu, a, o);
        b += __shfl_down_sync(0xffffffffu, b, o);
    }
    int w = threadIdx.x >> 5;
    if ((threadIdx.x & 31) == 0) { sb[w] = a; sb[w + 4] = b; }
    __syncthreads();
    float2 r;
    r.x = sb[0] + sb[1] + sb[2] + sb[3];
    r.y = sb[4] + sb[5] + sb[6] + sb[7];
    __syncthreads();
    return r;
}

#define LD4(p)  (*(const float4*)(p))
// streaming (evict-first) load — edge-weight data is read exactly once
#define LDS4(p) (__ldcs((const float4*)(p)))

// ---------------- fused main kernel: block per node, warp per edge (R7, proven) ----------------
__global__ __launch_bounds__(128, 8) void k_main(
    const float* __restrict__ feat,  const float* __restrict__ query,
    const int*   __restrict__ src,
    const float* __restrict__ ukw, const float* __restrict__ ukb,
    const float* __restrict__ vkw, const float* __restrict__ vkb,
    const float* __restrict__ ekw, const float* __restrict__ ekb,
    const float* __restrict__ uvw, const float* __restrict__ uvb,
    const float* __restrict__ vvw, const float* __restrict__ vvb,
    const float* __restrict__ evw, const float* __restrict__ evb,
    const float* __restrict__ nodew, const float* __restrict__ nodeb,
    const float* __restrict__ kg,  const float* __restrict__ kbt,
    const float* __restrict__ vg,  const float* __restrict__ vbt,
    const float* __restrict__ ng,  const float* __restrict__ nbt,
    float* __restrict__ out, float* __restrict__ attn)
{
    __shared__ float sb[8];
    __shared__ float swmax[4];
    __shared__ float sacc[4][DD];
    __shared__ float sscore[SCAP];

    const int n = blockIdx.x;
    const int t = threadIdx.x;
    const int w = t >> 5;
    const int l = t & 31;
    const int c = l << 2;
    const int off = g_off[n];
    const int deg = g_off[n + 1] - off;
    const float invD = 1.0f / DD;

    const float4 fv4 = LD4(feat  + n * DD + c);
    const float4 q4  = LD4(query + n * DD + c);
    const float4 kg4 = LD4(kg + c);
    const float4 kb4 = LD4(kbt + c);

    // ---- pass 1: key edge-FFN + LN + score (warp per edge, no barriers) ----
    float wmax = -3.402823466e38f;
    for (int i = w; i < deg; i += 4) {
        const int e = g_csr[off + i];
        const int s = src[e];
        const long eb = (long)e * DD + c;
        const float4 fu = LD4(feat + (long)s * DD + c);
        const float4 a1 = LDS4(ukw + eb), b1 = LDS4(ukb + eb);
        const float4 a2 = LDS4(vkw + eb), b2 = LDS4(vkb + eb);
        const float4 a3 = LDS4(ekw + eb), b3 = LDS4(ekb + eb);
        float4 h;
        h.x = fmaf(fu.x, a1.x, b1.x) + fmaf(fv4.x, a2.x, b2.x);
        h.y = fmaf(fu.y, a1.y, b1.y) + fmaf(fv4.y, a2.y, b2.y);
        h.z = fmaf(fu.z, a1.z, b1.z) + fmaf(fv4.z, a2.z, b2.z);
        h.w = fmaf(fu.w, a1.w, b1.w) + fmaf(fv4.w, a2.w, b2.w);
        h.x = gelu_erf(h.x); h.y = gelu_erf(h.y);
        h.z = gelu_erf(h.z); h.w = gelu_erf(h.w);
        h.x = fmaf(h.x, a3.x, b3.x);
        h.y = fmaf(h.y, a3.y, b3.y);
        h.z = fmaf(h.z, a3.z, b3.z);
        h.w = fmaf(h.w, a3.w, b3.w);
        float sum = h.x + h.y + h.z + h.w;
        float sq  = h.x * h.x + h.y * h.y + h.z * h.z + h.w * h.w;
        wred2(sum, sq);
        const float m   = sum * invD;
        const float var = fmaxf(sq * invD - m * m, 0.0f);
        const float rs  = rsqrtf(var + LN_EPS);
        float dot = ((h.x - m) * rs * kg4.x + kb4.x) * q4.x
                  + ((h.y - m) * rs * kg4.y + kb4.y) * q4.y
                  + ((h.z - m) * rs * kg4.z + kb4.z) * q4.z
                  + ((h.w - m) * rs * kg4.w + kb4.w) * q4.w;
        dot = wred(dot);
        if (l == 0 && i < SCAP) sscore[i] = dot;
        wmax = fmaxf(wmax, dot);
    }
    if (l == 0) swmax[w] = wmax;
    __syncthreads();
    const float smax = fmaxf(fmaxf(swmax[0], swmax[1]), fmaxf(swmax[2], swmax[3]));

    // ---- softmax denominator (parallel over threads, smem scores) ----
    float part = 0.0f;
    for (int i = t; i < deg; i += 128) part += __expf(sscore[i] - smax);
    const float ssum = bred1(part, sb);
    const float inv = (deg > 0) ? (1.0f / ssum) : 0.0f;

    // ---- pass 2: value edge-FFN + LN + weighted accumulation ----
    const float4 vg4 = LD4(vg + c);
    const float4 vb4 = LD4(vbt + c);
    float4 acc = make_float4(0.f, 0.f, 0.f, 0.f);
    for (int i = w; i < deg; i += 4) {
        const int e = g_csr[off + i];
        const float a = __expf(sscore[i] - smax) * inv;
        if (l == 0) __stcs(attn + e, a);
        const int s = src[e];
        const long eb = (long)e * DD + c;
        const float4 fu = LD4(feat + (long)s * DD + c);
        const float4 a1 = LDS4(uvw + eb), b1 = LDS4(uvb + eb);
        const float4 a2 = LDS4(vvw + eb), b2 = LDS4(vvb + eb);
        const float4 a3 = LDS4(evw + eb), b3 = LDS4(evb + eb);
        float4 h;
        h.x = fmaf(fu.x, a1.x, b1.x) + fmaf(fv4.x, a2.x, b2.x);
        h.y = fmaf(fu.y, a1.y, b1.y) + fmaf(fv4.y, a2.y, b2.y);
        h.z = fmaf(fu.z, a1.z, b1.z) + fmaf(fv4.z, a2.z, b2.z);
        h.w = fmaf(fu.w, a1.w, b1.w) + fmaf(fv4.w, a2.w, b2.w);
        h.x = gelu_erf(h.x); h.y = gelu_erf(h.y);
        h.z = gelu_erf(h.z); h.w = gelu_erf(h.w);
        h.x = fmaf(h.x, a3.x, b3.x);
        h.y = fmaf(h.y, a3.y, b3.y);
        h.z = fmaf(h.z, a3.z, b3.z);
        h.w = fmaf(h.w, a3.w, b3.w);
        float sum = h.x + h.y + h.z + h.w;
        float sq  = h.x * h.x + h.y * h.y + h.z * h.z + h.w * h.w;
        wred2(sum, sq);
        const float m   = sum * invD;
        const float var = fmaxf(sq * invD - m * m, 0.0f);
        const float rs  = rsqrtf(var + LN_EPS);
        acc.x = fmaf(((h.x - m) * rs) * vg4.x + vb4.x, a, acc.x);
        acc.y = fmaf(((h.y - m) * rs) * vg4.y + vb4.y, a, acc.y);
        acc.z = fmaf(((h.z - m) * rs) * vg4.z + vb4.z, a, acc.z);
        acc.w = fmaf(((h.w - m) * rs) * vg4.w + vb4.w, a, acc.w);
    }
    *(float4*)&sacc[w][c] = acc;
    __syncthreads();
    const float aT = sacc[0][t] + sacc[1][t] + sacc[2][t] + sacc[3][t];

    // ---- node FFN + residual + LN ----
    const float w0 = __ldcs(nodew + (n * 2 + 0) * DD + t);
    const float b0 = __ldcs(nodeb + (n * 2 + 0) * DD + t);
    const float w1 = __ldcs(nodew + (n * 2 + 1) * DD + t);
    const float b1 = __ldcs(nodeb + (n * 2 + 1) * DD + t);
    float h = gelu_erf(fmaf(aT, w0, b0));
    h = fmaf(h, w1, b1);
    const float rsd = aT + h;
    float2 r = bred2(rsd, rsd * rsd, sb);
    const float m   = r.x * invD;
    const float var = fmaxf(r.y * invD - m * m, 0.0f);
    out[n * DD + t] = (rsd - m) * rsqrtf(var + LN_EPS) * ng[t] + nbt[t];
}

// ---------------- launch ----------------
extern "C" void kernel_launch(void* const* d_in, const int* in_sizes, int n_in,
                              void* d_out, int out_size) {
    const float* feat  = (const float*)d_in[0];
    const float* query = (const float*)d_in[1];
    const int*   src   = (const int*)d_in[2];
    const int*   dst   = (const int*)d_in[3];
    const float* ukw = (const float*)d_in[4];
    const float* ukb = (const float*)d_in[5];
    const float* vkw = (const float*)d_in[6];
    const float* vkb = (const float*)d_in[7];
    const float* ekw = (const float*)d_in[8];
    const float* ekb = (const float*)d_in[9];
    const float* uvw = (const float*)d_in[10];
    const float* uvb = (const float*)d_in[11];
    const float* vvw = (const float*)d_in[12];
    const float* vvb = (const float*)d_in[13];
    const float* evw = (const float*)d_in[14];
    const float* evb = (const float*)d_in[15];
    const float* nodew = (const float*)d_in[16];
    const float* nodeb = (const float*)d_in[17];
    const float* kg  = (const float*)d_in[18];
    const float* vg  = (const float*)d_in[19];
    const float* ng  = (const float*)d_in[20];
    const float* kbt = (const float*)d_in[21];
    const float* vbt = (const float*)d_in[22];
    const float* nbt = (const float*)d_in[23];

    float* out  = (float*)d_out;            // [N, D]
    float* attn = out + (long)NN * DD;      // [E, 1]

    k_pre<<<NB, 256>>>(dst);
    k_main<<<NN, 128>>>(feat, query, src,
                        ukw, ukb, vkw, vkb, ekw, ekb,
                        uvw, uvb, vvw, vvb, evw, evb,
                        nodew, nodeb,
                        kg, kbt, vg, vbt, ng, nbt,
                        out, attn);
}

// round 13
// speedup vs baseline: 1.1815x; 1.0001x over previous
#include <cuda_runtime.h>
#include <math.h>

#define NN 20000
#define EE 320000
#define DD 128
#define SCAP 160         // smem score slots per node (max in-degree here ~45)
#define LN_EPS 1e-5f
#define NB 256           // prelude grid: 2 blocks/SM co-resident (<= 296 capacity)
#define SCB 79           // scan blocks: 79*256 = 20224 >= NN

// ---------------- scratch (no allocations allowed) ----------------
__device__ int   g_counts[NN];          // zero at load; reset each call (phase B2)
__device__ int   g_off[NN + 1];
__device__ int   g_cur[NN];
__device__ int   g_csr[EE];
__device__ int   g_bsum[SCB];
__device__ volatile unsigned g_gen = 0; // grid-barrier generation (monotonic)
__device__ unsigned g_arrive = 0;       // grid-barrier arrive counter (self-resetting)

// ---------------- grid barrier (all NB blocks guaranteed resident) ----------------
__device__ __forceinline__ void grid_sync() {
    __syncthreads();
    if (threadIdx.x == 0) {
        __threadfence();
        unsigned gen = g_gen;
        if (atomicAdd(&g_arrive, 1u) == NB - 1u) {
            g_arrive = 0;
            __threadfence();
            g_gen = gen + 1u;
        } else {
            while (g_gen == gen) { }
            __threadfence();
        }
    }
    __syncthreads();
}

__device__ __forceinline__ int wscan_incl(int v, int l) {
    #pragma unroll
    for (int o = 1; o < 32; o <<= 1) {
        int u = __shfl_up_sync(0xffffffffu, v, o);
        if (l >= o) v += u;
    }
    return v;
}

// ---------------- fused CSR build: hist -> scan -> offsets(+redundant prefix) -> scatter ----------------
__global__ __launch_bounds__(256, 2) void k_pre(const int* __restrict__ dst) {
    const int t   = threadIdx.x;
    const int bid = blockIdx.x;
    const int l   = t & 31;
    const int wid = t >> 5;
    __shared__ int wsum[8];
    __shared__ int isum[8];
    __shared__ int sbtot;

    // ---- phase A: histogram ----
    for (int i = bid * 256 + t; i < EE; i += NB * 256)
        atomicAdd(&g_counts[dst[i]], 1);
    grid_sync();

    // ---- phase B1: per-block scan over 256 nodes ----
    int ex_local = 0;
    if (bid < SCB) {
        const int node = bid * 256 + t;
        const int cval = (node < NN) ? g_counts[node] : 0;
        int incl = wscan_incl(cval, l);
        if (l == 31) wsum[wid] = incl;
        __syncthreads();
        if (t < 8) {
            int v = wsum[t];
            #pragma unroll
            for (int o = 1; o < 8; o <<= 1) {
                int u = __shfl_up_sync(0xffu, v, o);
                if (t >= o) v += u;
            }
            wsum[t] = v;
        }
        __syncthreads();
        ex_local = ((wid == 0) ? 0 : wsum[wid - 1]) + incl - cval;
        if (t == 0) sbtot = 0;           // init before reuse below
        if (t == 255) g_bsum[bid] = wsum[7];
        __syncthreads();
        if (t == 255) sbtot = wsum[7];   // keep block total in smem
        __syncthreads();
    }
    grid_sync();

    // ---- phase B2: every scan block computes its own prefix (redundant, no extra sync) ----
    if (bid < SCB) {
        int v = (t < bid) ? g_bsum[t] : 0;    // bid <= 78 < 256
        #pragma unroll
        for (int o = 16; o; o >>= 1) v += __shfl_xor_sync(0xffffffffu, v, o);
        if (l == 0) isum[wid] = v;
        __syncthreads();
        const int base = isum[0] + isum[1] + isum[2] + isum[3]
                       + isum[4] + isum[5] + isum[6] + isum[7];
        const int node = bid * 256 + t;
        if (node < NN) {
            const int off = base + ex_local;
            g_off[node] = off;
            g_cur[node] = off;
            g_counts[node] = 0;               // restore invariant for next call
        }
        if (bid == SCB - 1 && t == 0) g_off[NN] = base + sbtot;
    }
    grid_sync();

    // ---- phase C: scatter edge ids ----
    for (int i = bid * 256 + t; i < EE; i += NB * 256) {
        int p = atomicAdd(&g_cur[dst[i]], 1);
        g_csr[p] = i;
    }
}

// ---------------- helpers ----------------
__device__ __forceinline__ float gelu_erf(float x) {
    return 0.5f * x * (1.0f + erff(x * 0.70710678118654752440f));
}

__device__ __forceinline__ float wred(float a) {
    #pragma unroll
    for (int o = 16; o; o >>= 1) a += __shfl_xor_sync(0xffffffffu, a, o);
    return a;
}

__device__ __forceinline__ void wred2(float& a, float& b) {
    #pragma unroll
    for (int o = 16; o; o >>= 1) {
        a += __shfl_xor_sync(0xffffffffu, a, o);
        b += __shfl_xor_sync(0xffffffffu, b, o);
    }
}

__device__ __forceinline__ float bred1(float a, volatile float* sb) {
    #pragma unroll
    for (int o = 16; o; o >>= 1) a += __shfl_down_sync(0xffffffffu, a, o);
    if ((threadIdx.x & 31) == 0) sb[threadIdx.x >> 5] = a;
    __syncthreads();
    a = sb[0] + sb[1] + sb[2] + sb[3];
    __syncthreads();
    return a;
}

__device__ __forceinline__ float2 bred2(float a, float b, volatile float* sb) {
    #pragma unroll
    for (int o = 16; o; o >>= 1) {
        a += __shfl_down_sync(0xffffffffu, a, o);
        b += __shfl_down_sync(0xffffffffu, b, o);
    }
    int w = threadIdx.x >> 5;
    if ((threadIdx.x & 31) == 0) { sb[w] = a; sb[w + 4] = b; }
    __syncthreads();
    float2 r;
    r.x = sb[0] + sb[1] + sb[2] + sb[3];
    r.y = sb[4] + sb[5] + sb[6] + sb[7];
    __syncthreads();
    return r;
}

#define LD4(p)  (*(const float4*)(p))
// streaming (evict-first) load — edge-weight data is read exactly once
#define LDS4(p) (__ldcs((const float4*)(p)))

// ---------------- fused main kernel: block per node, warp per edge (R7, proven) ----------------
__global__ __launch_bounds__(128, 8) void k_main(
    const float* __restrict__ feat,  const float* __restrict__ query,
    const int*   __restrict__ src,
    const float* __restrict__ ukw, const float* __restrict__ ukb,
    const float* __restrict__ vkw, const float* __restrict__ vkb,
    const float* __restrict__ ekw, const float* __restrict__ ekb,
    const float* __restrict__ uvw, const float* __restrict__ uvb,
    const float* __restrict__ vvw, const float* __restrict__ vvb,
    const float* __restrict__ evw, const float* __restrict__ evb,
    const float* __restrict__ nodew, const float* __restrict__ nodeb,
    const float* __restrict__ kg,  const float* __restrict__ kbt,
    const float* __restrict__ vg,  const float* __restrict__ vbt,
    const float* __restrict__ ng,  const float* __restrict__ nbt,
    float* __restrict__ out, float* __restrict__ attn)
{
    __shared__ float sb[8];
    __shared__ float swmax[4];
    __shared__ float sacc[4][DD];
    __shared__ float sscore[SCAP];

    const int n = blockIdx.x;
    const int t = threadIdx.x;
    const int w = t >> 5;
    const int l = t & 31;
    const int c = l << 2;
    const int off = g_off[n];
    const int deg = g_off[n + 1] - off;
    const float invD = 1.0f / DD;

    const float4 fv4 = LD4(feat  + n * DD + c);
    const float4 q4  = LD4(query + n * DD + c);
    const float4 kg4 = LD4(kg + c);
    const float4 kb4 = LD4(kbt + c);

    // ---- pass 1: key edge-FFN + LN + score (warp per edge, no barriers) ----
    float wmax = -3.402823466e38f;
    for (int i = w; i < deg; i += 4) {
        const int e = g_csr[off + i];
        const int s = src[e];
        const long eb = (long)e * DD + c;
        const float4 fu = LD4(feat + (long)s * DD + c);
        const float4 a1 = LDS4(ukw + eb), b1 = LDS4(ukb + eb);
        const float4 a2 = LDS4(vkw + eb), b2 = LDS4(vkb + eb);
        const float4 a3 = LDS4(ekw + eb), b3 = LDS4(ekb + eb);
        float4 h;
        h.x = fmaf(fu.x, a1.x, b1.x) + fmaf(fv4.x, a2.x, b2.x);
        h.y = fmaf(fu.y, a1.y, b1.y) + fmaf(fv4.y, a2.y, b2.y);
        h.z = fmaf(fu.z, a1.z, b1.z) + fmaf(fv4.z, a2.z, b2.z);
        h.w = fmaf(fu.w, a1.w, b1.w) + fmaf(fv4.w, a2.w, b2.w);
        h.x = gelu_erf(h.x); h.y = gelu_erf(h.y);
        h.z = gelu_erf(h.z); h.w = gelu_erf(h.w);
        h.x = fmaf(h.x, a3.x, b3.x);
        h.y = fmaf(h.y, a3.y, b3.y);
        h.z = fmaf(h.z, a3.z, b3.z);
        h.w = fmaf(h.w, a3.w, b3.w);
        float sum = h.x + h.y + h.z + h.w;
        float sq  = h.x * h.x + h.y * h.y + h.z * h.z + h.w * h.w;
        wred2(sum, sq);
        const float m   = sum * invD;
        const float var = fmaxf(sq * invD - m * m, 0.0f);
        const float rs  = rsqrtf(var + LN_EPS);
        float dot = ((h.x - m) * rs * kg4.x + kb4.x) * q4.x
                  + ((h.y - m) * rs * kg4.y + kb4.y) * q4.y
                  + ((h.z - m) * rs * kg4.z + kb4.z) * q4.z
                  + ((h.w - m) * rs * kg4.w + kb4.w) * q4.w;
        dot = wred(dot);
        if (l == 0 && i < SCAP) sscore[i] = dot;
        wmax = fmaxf(wmax, dot);
    }
    if (l == 0) swmax[w] = wmax;
    __syncthreads();
    const float smax = fmaxf(fmaxf(swmax[0], swmax[1]), fmaxf(swmax[2], swmax[3]));

    // ---- softmax denominator (parallel over threads, smem scores) ----
    float part = 0.0f;
    for (int i = t; i < deg; i += 128) part += __expf(sscore[i] - smax);
    const float ssum = bred1(part, sb);
    const float inv = (deg > 0) ? (1.0f / ssum) : 0.0f;

    // ---- pass 2: value edge-FFN + LN + weighted accumulation ----
    const float4 vg4 = LD4(vg + c);
    const float4 vb4 = LD4(vbt + c);
    float4 acc = make_float4(0.f, 0.f, 0.f, 0.f);
    for (int i = w; i < deg; i += 4) {
        const int e = g_csr[off + i];
        const float a = __expf(sscore[i] - smax) * inv;
        if (l == 0) __stcs(attn + e, a);
        const int s = src[e];
        const long eb = (long)e * DD + c;
        const float4 fu = LD4(feat + (long)s * DD + c);
        const float4 a1 = LDS4(uvw + eb), b1 = LDS4(uvb + eb);
        const float4 a2 = LDS4(vvw + eb), b2 = LDS4(vvb + eb);
        const float4 a3 = LDS4(evw + eb), b3 = LDS4(evb + eb);
        float4 h;
        h.x = fmaf(fu.x, a1.x, b1.x) + fmaf(fv4.x, a2.x, b2.x);
        h.y = fmaf(fu.y, a1.y, b1.y) + fmaf(fv4.y, a2.y, b2.y);
        h.z = fmaf(fu.z, a1.z, b1.z) + fmaf(fv4.z, a2.z, b2.z);
        h.w = fmaf(fu.w, a1.w, b1.w) + fmaf(fv4.w, a2.w, b2.w);
        h.x = gelu_erf(h.x); h.y = gelu_erf(h.y);
        h.z = gelu_erf(h.z); h.w = gelu_erf(h.w);
        h.x = fmaf(h.x, a3.x, b3.x);
        h.y = fmaf(h.y, a3.y, b3.y);
        h.z = fmaf(h.z, a3.z, b3.z);
        h.w = fmaf(h.w, a3.w, b3.w);
        float sum = h.x + h.y + h.z + h.w;
        float sq  = h.x * h.x + h.y * h.y + h.z * h.z + h.w * h.w;
        wred2(sum, sq);
        const float m   = sum * invD;
        const float var = fmaxf(sq * invD - m * m, 0.0f);
        const float rs  = rsqrtf(var + LN_EPS);
        acc.x = fmaf(((h.x - m) * rs) * vg4.x + vb4.x, a, acc.x);
        acc.y = fmaf(((h.y - m) * rs) * vg4.y + vb4.y, a, acc.y);
        acc.z = fmaf(((h.z - m) * rs) * vg4.z + vb4.z, a, acc.z);
        acc.w = fmaf(((h.w - m) * rs) * vg4.w + vb4.w, a, acc.w);
    }
    *(float4*)&sacc[w][c] = acc;
    __syncthreads();
    const float aT = sacc[0][t] + sacc[1][t] + sacc[2][t] + sacc[3][t];

    // ---- node FFN + residual + LN ----
    const float w0 = __ldcs(nodew + (n * 2 + 0) * DD + t);
    const float b0 = __ldcs(nodeb + (n * 2 + 0) * DD + t);
    const float w1 = __ldcs(nodew + (n * 2 + 1) * DD + t);
    const float b1 = __ldcs(nodeb + (n * 2 + 1) * DD + t);
    float h = gelu_erf(fmaf(aT, w0, b0));
    h = fmaf(h, w1, b1);
    const float rsd = aT + h;
    float2 r = bred2(rsd, rsd * rsd, sb);
    const float m   = r.x * invD;
    const float var = fmaxf(r.y * invD - m * m, 0.0f);
    out[n * DD + t] = (rsd - m) * rsqrtf(var + LN_EPS) * ng[t] + nbt[t];
}

// ---------------- launch ----------------
extern "C" void kernel_launch(void* const* d_in, const int* in_sizes, int n_in,
                              void* d_out, int out_size) {
    const float* feat  = (const float*)d_in[0];
    const float* query = (const float*)d_in[1];
    const int*   src   = (const int*)d_in[2];
    const int*   dst   = (const int*)d_in[3];
    const float* ukw = (const float*)d_in[4];
    const float* ukb = (const float*)d_in[5];
    const float* vkw = (const float*)d_in[6];
    const float* vkb = (const float*)d_in[7];
    const float* ekw = (const float*)d_in[8];
    const float* ekb = (const float*)d_in[9];
    const float* uvw = (const float*)d_in[10];
    const float* uvb = (const float*)d_in[11];
    const float* vvw = (const float*)d_in[12];
    const float* vvb = (const float*)d_in[13];
    const float* evw = (const float*)d_in[14];
    const float* evb = (const float*)d_in[15];
    const float* nodew = (const float*)d_in[16];
    const float* nodeb = (const float*)d_in[17];
    const float* kg  = (const float*)d_in[18];
    const float* vg  = (const float*)d_in[19];
    const float* ng  = (const float*)d_in[20];
    const float* kbt = (const float*)d_in[21];
    const float* vbt = (const float*)d_in[22];
    const float* nbt = (const float*)d_in[23];

    float* out  = (float*)d_out;            // [N, D]
    float* attn = out + (long)NN * DD;      // [E, 1]

    k_pre<<<NB, 256>>>(dst);
    k_main<<<NN, 128>>>(feat, query, src,
                        ukw, ukb, vkw, vkb, ekw, ekb,
                        uvw, uvb, vvw, vvb, evw, evb,
                        nodew, nodeb,
                        kg, kbt, vg, vbt, ng, nbt,
                        out, attn);
}